// round 15
// baseline (speedup 1.0000x reference)
#include <cuda_runtime.h>
#include <cuda_fp16.h>
#include <cstdint>

#define BB 32
#define TT 2048
#define HH 1024
#define UU 1024
#define BT (BB*TT)

// score GEMM tiling (fp16 mainloop)
#define TM 128
#define TN 128
#define KC 64            // K per chunk = 128B data per row
#define NCHUNK (HH/KC)   // 16
#define NBLK (UU/TN)     // 8
#define STAGES 2

// SMEM: 128B data + 32B pad -> pitch 160B (40 words, ≡8 mod 32: LDS.64 conflict-free)
#define PITCHB 160
#define TILEB (128*PITCHB)          // 20480
#define BUFBYTES (2*TILEB)          // 40960
#define SMEM_TOTAL (STAGES*BUFBYTES)   // 81920  (s_red aliases buffer 0)

// k-interleave perm within each 16-half block: stored[4t+{0,1,2,3}] = in[{2t,2t+1,2t+8,2t+9}]
// => lane tc's mma fragment (k=2tc,2tc+1,2tc+8,2tc+9) is 8 contiguous bytes at 8*tc.

// Scratch
__device__ __half g_enc16[(size_t)BT*HH];   // fp16 enc, k-interleaved per 16-block
__device__ __half g_UaT16[(size_t)UU*HH];   // Ua^T fp16, same k-interleave
__device__ float g_dec_proj[BB*UU];
__device__ float g_score_part[NBLK][BT];
__device__ float g_score[BT];
__device__ float g_ctx_part[16][BB*HH];

__device__ __forceinline__ float tanh_fast(float x) {
    float y; asm("tanh.approx.f32 %0, %1;" : "=f"(y) : "f"(x)); return y;
}
__device__ __forceinline__ uint32_t smem_u32(const void* p) {
    uint32_t a;
    asm("{ .reg .u64 t; cvta.to.shared.u64 t, %1; cvt.u32.u64 %0, t; }" : "=r"(a) : "l"(p));
    return a;
}
__device__ __forceinline__ void cpasync16(uint32_t dst, const void* src) {
    asm volatile("cp.async.cg.shared.global [%0], [%1], 16;" :: "r"(dst), "l"(src));
}
__device__ __forceinline__ void mma_f16(float* d, uint32_t a0, uint32_t a1,
                                        uint32_t a2, uint32_t a3,
                                        uint32_t b0, uint32_t b1) {
    asm volatile(
        "mma.sync.aligned.m16n8k16.row.col.f32.f16.f16.f32 "
        "{%0,%1,%2,%3}, {%4,%5,%6,%7}, {%8,%9}, {%0,%1,%2,%3};"
        : "+f"(d[0]), "+f"(d[1]), "+f"(d[2]), "+f"(d[3])
        : "r"(a0), "r"(a1), "r"(a2), "r"(a3), "r"(b0), "r"(b1));
}

// ---------------------------------------------------------------------------
// Fused prep: [0,128) dec_proj | [128,1152) Ua transpose | [1152,...) enc->fp16
// ---------------------------------------------------------------------------
__global__ __launch_bounds__(256) void k_prep(const float* __restrict__ enc,
                                              const float* __restrict__ dec,
                                              const float* __restrict__ Wa,
                                              const float* __restrict__ Ua) {
    __shared__ float sh[1056];
    const int bid = blockIdx.x;
    const int tid = threadIdx.x;

    if (bid < 128) {
        // dec_proj[b,u] = dec_hidden[b,:] @ Wa
        int b = bid >> 2;
        int u = (bid & 3) * 256 + tid;
        for (int i = tid; i < HH; i += 256) sh[i] = dec[b * HH + i];
        __syncthreads();
        float acc = 0.f;
        #pragma unroll 16
        for (int h = 0; h < HH; ++h) acc += sh[h] * Wa[(size_t)h * UU + u];
        g_dec_proj[b * UU + u] = acc;
    } else if (bid < 1152) {
        // Ua[k][u] -> g_UaT16[u][k'] (fp16, k-interleaved)
        float (*t)[33] = (float(*)[33])sh;
        int q = bid - 128;
        int bu = (q & 31) * 32, bk = (q >> 5) * 32;
        int tx = tid & 31, ty = tid >> 5;
        #pragma unroll
        for (int i = 0; i < 32; i += 8)
            t[ty + i][tx] = Ua[(size_t)(bk + ty + i) * UU + bu + tx];
        __syncthreads();
        #pragma unroll
        for (int i = 0; i < 32; i += 8) {
            int k = bk + tx;
            int r = k & 15;
            int pos = (r < 8) ? ((r >> 1) * 4 + (r & 1))
                              : (((r - 8) >> 1) * 4 + 2 + (r & 1));
            int ks = (k & ~15) + pos;
            g_UaT16[(size_t)(bu + ty + i) * HH + ks] = __float2half(t[tx][ty + i]);
        }
    } else {
        // enc fp32 -> fp16, one 16-half k-block per thread, interleaved store
        size_t i = (size_t)(bid - 1152) * 256 + tid;   // over BT*HH/16
        const float* src = enc + i * 16;
        float4 v0 = ((const float4*)src)[0];
        float4 v1 = ((const float4*)src)[1];
        float4 v2 = ((const float4*)src)[2];
        float4 v3 = ((const float4*)src)[3];
        // in[0..15] = v0.xyzw v1.xyzw v2.xyzw v3.xyzw
        uint4 o0, o1;
        ((__half2*)&o0)[0] = __floats2half2_rn(v0.x, v0.y);   // 0,1
        ((__half2*)&o0)[1] = __floats2half2_rn(v2.x, v2.y);   // 8,9
        ((__half2*)&o0)[2] = __floats2half2_rn(v0.z, v0.w);   // 2,3
        ((__half2*)&o0)[3] = __floats2half2_rn(v2.z, v2.w);   // 10,11
        ((__half2*)&o1)[0] = __floats2half2_rn(v1.x, v1.y);   // 4,5
        ((__half2*)&o1)[1] = __floats2half2_rn(v3.x, v3.y);   // 12,13
        ((__half2*)&o1)[2] = __floats2half2_rn(v1.z, v1.w);   // 6,7
        ((__half2*)&o1)[3] = __floats2half2_rn(v3.z, v3.w);   // 14,15
        ((uint4*)g_enc16)[2 * i]     = o0;
        ((uint4*)g_enc16)[2 * i + 1] = o1;
    }
}

// ---------------------------------------------------------------------------
// Dominant kernel: fp16 mma.sync m16n8k16 GEMM with fused tanh/Va epilogue.
// KC=64 chunks, 2-stage cp.async pipeline, LDS.64 fragments, 2 CTA/SM.
// grid = (NBLK=8, BT/TM=512), block = 256 (8 warps of 64x32 tiles).
// ---------------------------------------------------------------------------
__global__ void __launch_bounds__(256, 2)
k_score_mma(const float* __restrict__ Va) {
    extern __shared__ __align__(16) char smem[];
    const uint32_t sb = smem_u32(smem);
    const int tid  = threadIdx.x;
    const int lane = tid & 31;
    const int wid  = tid >> 5;
    const int g    = lane >> 2;       // groupID
    const int tc   = lane & 3;        // threadID_in_group
    const int Mw   = wid & 1;         // warp M row (0/1)
    const int Nw   = wid >> 1;        // warp N col (0..3)

    const int u0 = blockIdx.x * TN;
    const int r0 = blockIdx.y * TM;
    const int b  = blockIdx.y >> 4;   // r0 / TT

    const __half* Ag = g_enc16 + (size_t)r0 * HH;
    const __half* Bg = g_UaT16 + (size_t)u0 * HH;

    // staging: 128 rows x 8 granules (16B) per tile; 4 A + 4 B per thread/stage
    const int st_row = tid >> 3, st_g = tid & 7;

    float d[4][4][4] = {};   // [Mtile][Ntile][reg]

    // ---- prologue: stage chunk 0 ----
    {
        const uint32_t ab = sb;
        #pragma unroll
        for (int j = 0; j < 4; ++j) {
            int row = st_row + 32 * j;
            cpasync16(ab + row * PITCHB + st_g * 16,
                      Ag + (size_t)row * HH + st_g * 8);
            cpasync16(ab + TILEB + row * PITCHB + st_g * 16,
                      Bg + (size_t)row * HH + st_g * 8);
        }
        asm volatile("cp.async.commit_group;" ::: "memory");
    }

    // per-lane fragment base offsets (bytes, within a buffer)
    const uint32_t aLane = (uint32_t)((Mw * 64 + g) * PITCHB + tc * 8);
    const uint32_t bLane = (uint32_t)((Nw * 32 + g) * PITCHB + tc * 8);

    for (int c = 0; c < NCHUNK; ++c) {
        asm volatile("cp.async.wait_group 0;" ::: "memory");
        __syncthreads();
        const uint32_t bufo = (c & 1) * BUFBYTES;

        // issue chunk c+1 into the other buffer (its readers finished pre-sync)
        if (c + 1 < NCHUNK) {
            const uint32_t ab = sb + ((c + 1) & 1) * BUFBYTES;
            const int k0 = (c + 1) * KC;
            #pragma unroll
            for (int j = 0; j < 4; ++j) {
                int row = st_row + 32 * j;
                cpasync16(ab + row * PITCHB + st_g * 16,
                          Ag + (size_t)row * HH + k0 + st_g * 8);
                cpasync16(ab + TILEB + row * PITCHB + st_g * 16,
                          Bg + (size_t)row * HH + k0 + st_g * 8);
            }
            asm volatile("cp.async.commit_group;" ::: "memory");
        }

        // ---- compute chunk c: 4 K-steps of 16 (LDS.64 fragments) ----
        #pragma unroll
        for (int s = 0; s < 4; ++s) {
            uint2 alo[4], ahi[4];
            #pragma unroll
            for (int i = 0; i < 4; ++i) {
                const char* p = smem + bufo + aLane + i * 16 * PITCHB + s * 32;
                alo[i] = *(const uint2*)(p);                 // a0, a2
                ahi[i] = *(const uint2*)(p + 8 * PITCHB);    // a1, a3
            }
            #pragma unroll
            for (int jn = 0; jn < 4; ++jn) {
                const char* q = smem + bufo + TILEB + bLane
                              + jn * 8 * PITCHB + s * 32;
                uint2 bb = *(const uint2*)(q);               // b0, b1
                #pragma unroll
                for (int i = 0; i < 4; ++i)
                    mma_f16(d[i][jn], alo[i].x, ahi[i].x, alo[i].y, ahi[i].y,
                            bb.x, bb.y);
            }
        }
    }

    // ---- fused epilogue: tanh(d + dec)*Va, reduce over u ----
    float vdec[4][2], vva[4][2];
    #pragma unroll
    for (int jn = 0; jn < 4; ++jn)
        #pragma unroll
        for (int rr = 0; rr < 2; ++rr) {
            int ul = Nw * 32 + jn * 8 + tc * 2 + rr;
            vdec[jn][rr] = g_dec_proj[b * UU + u0 + ul];
            vva[jn][rr]  = Va[u0 + ul];
        }

    float rowacc[4][2] = {};
    #pragma unroll
    for (int i = 0; i < 4; ++i)
        #pragma unroll
        for (int jn = 0; jn < 4; ++jn)
            #pragma unroll
            for (int r = 0; r < 4; ++r) {
                float v = tanh_fast(d[i][jn][r] + vdec[jn][r & 1]) * vva[jn][r & 1];
                rowacc[i][r >> 1] += v;
            }
    #pragma unroll
    for (int i = 0; i < 4; ++i)
        #pragma unroll
        for (int h = 0; h < 2; ++h) {
            float v = rowacc[i][h];
            v += __shfl_xor_sync(0xffffffffu, v, 1);
            v += __shfl_xor_sync(0xffffffffu, v, 2);
            rowacc[i][h] = v;
        }

    // s_red aliases stage buffer 0 — wait for all warps to finish the mainloop
    __syncthreads();
    float* s_red = (float*)smem;
    if (tc == 0) {
        #pragma unroll
        for (int i = 0; i < 4; ++i)
            #pragma unroll
            for (int h = 0; h < 2; ++h) {
                int m = Mw * 64 + i * 16 + h * 8 + g;
                s_red[m * 4 + Nw] = rowacc[i][h];
            }
    }
    __syncthreads();
    if (tid < TM) {
        float s = s_red[tid * 4] + s_red[tid * 4 + 1]
                + s_red[tid * 4 + 2] + s_red[tid * 4 + 3];
        g_score_part[blockIdx.x][r0 + tid] = s;
    }
}

// ---------------------------------------------------------------------------
// Softmax over T (sums the 8 N-block partials). grid (B), 256 thr.
// ---------------------------------------------------------------------------
__global__ __launch_bounds__(256) void k_softmax() {
    int b = blockIdx.x, tid = threadIdx.x;
    __shared__ float sm[256];
    float* sc = g_score + b * TT;

    float m = -1e30f;
    for (int t = tid; t < TT; t += 256) {
        float v = 0.f;
        #pragma unroll
        for (int p = 0; p < NBLK; ++p) v += g_score_part[p][b * TT + t];
        sc[t] = v;
        m = fmaxf(m, v);
    }
    sm[tid] = m; __syncthreads();
    for (int s = 128; s > 0; s >>= 1) {
        if (tid < s) sm[tid] = fmaxf(sm[tid], sm[tid + s]);
        __syncthreads();
    }
    m = sm[0]; __syncthreads();

    float sum = 0.f;
    for (int t = tid; t < TT; t += 256) {
        float e = __expf(sc[t] - m);
        sc[t] = e; sum += e;
    }
    sm[tid] = sum; __syncthreads();
    for (int s = 128; s > 0; s >>= 1) {
        if (tid < s) sm[tid] += sm[tid + s];
        __syncthreads();
    }
    float inv = 1.f / sm[0];
    for (int t = tid; t < TT; t += 256) sc[t] *= inv;
}

// ---------------------------------------------------------------------------
// Context from (k-interleaved) fp16 enc: grid (B, 2, 16), block 256.
// Each thread: one stored half2 slot x 128 t's; output index de-permuted.
// ---------------------------------------------------------------------------
__global__ __launch_bounds__(256) void k_ctx_part() {
    int b = blockIdx.x, hc = blockIdx.y, tc = blockIdx.z;
    int t0 = tc * 128;
    __shared__ float s_al[128];
    if (threadIdx.x < 128) s_al[threadIdx.x] = g_score[b * TT + t0 + threadIdx.x];
    __syncthreads();

    int slot = hc * 256 + threadIdx.x;        // stored half2 slot (0..511)
    const __half2* e = (const __half2*)g_enc16
                     + ((size_t)b * TT + t0) * (HH/2) + slot;
    float ax = 0.f, ay = 0.f;
    #pragma unroll 16
    for (int t = 0; t < 128; ++t) {
        float2 f = __half22float2(e[(size_t)t * (HH/2)]);
        ax += s_al[t] * f.x;
        ay += s_al[t] * f.y;
    }
    // de-permute: stored slot q within its 8-slot block -> real half2 index
    int kb = slot >> 3, q = slot & 7;
    int real = kb * 8 + ((q & 1) ? (q >> 1) + 4 : (q >> 1));
    ((float2*)&g_ctx_part[tc][b * HH])[real] = make_float2(ax, ay);
}

__global__ __launch_bounds__(256) void k_ctx_final(float* __restrict__ out) {
    int idx = blockIdx.x * 256 + threadIdx.x;
    float s = 0.f;
    #pragma unroll
    for (int p = 0; p < 16; ++p) s += g_ctx_part[p][idx];
    out[idx] = s;
}

// ---------------------------------------------------------------------------
extern "C" void kernel_launch(void* const* d_in, const int* in_sizes, int n_in,
                              void* d_out, int out_size) {
    const float* enc = (const float*)d_in[0];
    const float* dec = (const float*)d_in[1];
    const float* Wa  = (const float*)d_in[2];
    const float* Ua  = (const float*)d_in[3];
    const float* Va  = (const float*)d_in[4];
    float* out = (float*)d_out;

    cudaFuncSetAttribute(k_score_mma,
                         cudaFuncAttributeMaxDynamicSharedMemorySize,
                         SMEM_TOTAL);

    k_prep<<<1152 + (BT * (HH / 16)) / 256, 256>>>(enc, dec, Wa, Ua);
    k_score_mma<<<dim3(NBLK, BT / TM), 256, SMEM_TOTAL>>>(Va);
    k_softmax<<<BB, 256>>>();
    k_ctx_part<<<dim3(BB, 2, 16), 256>>>();
    k_ctx_final<<<(BB * HH) / 256, 256>>>(out);
}

// round 16
// speedup vs baseline: 1.0258x; 1.0258x over previous
#include <cuda_runtime.h>
#include <cuda_fp16.h>
#include <cstdint>

#define BB 32
#define TT 2048
#define HH 1024
#define UU 1024
#define BT (BB*TT)

// score GEMM tiling (fp16 mainloop) — R13 proven shape
#define TM 128
#define TN 128
#define KC 64            // K per chunk (fp16 elems) = 128B per row
#define NCHUNK (HH/KC)   // 16
#define NBLK (UU/TN)     // 8
#define STAGES 3

// SMEM: 64 fp16 = 128B data per row + 16B pad -> pitch 144B
// frag LDS banks: word = (36*g + tc) % 32 = (4g + tc) % 32, all 32 distinct
#define PITCHB 144
#define TILEB (128*PITCHB)          // 18432
#define BUFBYTES (2*TILEB)          // 36864
#define SMEM_TOTAL (STAGES*BUFBYTES)   // 110592  (s_red aliases buffer 0)

// Scratch
__device__ __half g_enc16[(size_t)BT*HH];   // fp16 copy of enc (128MB)
__device__ __half g_UaT16[(size_t)UU*HH];   // Ua transposed to [u][k], fp16
__device__ float g_dec_proj[BB*UU];
__device__ float g_score_part[NBLK][BT];
__device__ float g_score[BT];
__device__ float g_ctx_part[16][BB*HH];

__device__ __forceinline__ float tanh_fast(float x) {
    float y; asm("tanh.approx.f32 %0, %1;" : "=f"(y) : "f"(x)); return y;
}
__device__ __forceinline__ uint32_t smem_u32(const void* p) {
    uint32_t a;
    asm("{ .reg .u64 t; cvta.to.shared.u64 t, %1; cvt.u32.u64 %0, t; }" : "=r"(a) : "l"(p));
    return a;
}
__device__ __forceinline__ void cpasync16(uint32_t dst, const void* src) {
    asm volatile("cp.async.cg.shared.global [%0], [%1], 16;" :: "r"(dst), "l"(src));
}
__device__ __forceinline__ void mma_f16(float* d, const uint32_t* a,
                                        uint32_t b0, uint32_t b1) {
    asm volatile(
        "mma.sync.aligned.m16n8k16.row.col.f32.f16.f16.f32 "
        "{%0,%1,%2,%3}, {%4,%5,%6,%7}, {%8,%9}, {%0,%1,%2,%3};"
        : "+f"(d[0]), "+f"(d[1]), "+f"(d[2]), "+f"(d[3])
        : "r"(a[0]), "r"(a[1]), "r"(a[2]), "r"(a[3]), "r"(b0), "r"(b1));
}

// ---------------------------------------------------------------------------
// Fused prep: [0,128) dec_proj | [128,1152) Ua transpose | [1152,...) enc->fp16
// ---------------------------------------------------------------------------
__global__ __launch_bounds__(256) void k_prep(const float* __restrict__ enc,
                                              const float* __restrict__ dec,
                                              const float* __restrict__ Wa,
                                              const float* __restrict__ Ua) {
    __shared__ float sh[1056];
    const int bid = blockIdx.x;
    const int tid = threadIdx.x;

    if (bid < 128) {
        // dec_proj[b,u] = dec_hidden[b,:] @ Wa
        int b = bid >> 2;
        int u = (bid & 3) * 256 + tid;
        for (int i = tid; i < HH; i += 256) sh[i] = dec[b * HH + i];
        __syncthreads();
        float acc = 0.f;
        #pragma unroll 16
        for (int h = 0; h < HH; ++h) acc += sh[h] * Wa[(size_t)h * UU + u];
        g_dec_proj[b * UU + u] = acc;
    } else if (bid < 1152) {
        // Ua[k][u] -> g_UaT16[u][k] (fp16)
        float (*t)[33] = (float(*)[33])sh;
        int q = bid - 128;
        int bu = (q & 31) * 32, bk = (q >> 5) * 32;
        int tx = tid & 31, ty = tid >> 5;
        #pragma unroll
        for (int i = 0; i < 32; i += 8)
            t[ty + i][tx] = Ua[(size_t)(bk + ty + i) * UU + bu + tx];
        __syncthreads();
        #pragma unroll
        for (int i = 0; i < 32; i += 8)
            g_UaT16[(size_t)(bu + ty + i) * HH + bk + tx] = __float2half(t[tx][ty + i]);
    } else {
        // enc fp32 -> fp16: 8 floats per thread (2x float4 read, 1x uint4 write)
        size_t i = (size_t)(bid - 1152) * 256 + tid;   // over BT*HH/8
        const float4* src = (const float4*)enc + 2 * i;
        float4 v0 = src[0], v1 = src[1];
        uint4 o;
        ((__half2*)&o)[0] = __floats2half2_rn(v0.x, v0.y);
        ((__half2*)&o)[1] = __floats2half2_rn(v0.z, v0.w);
        ((__half2*)&o)[2] = __floats2half2_rn(v1.x, v1.y);
        ((__half2*)&o)[3] = __floats2half2_rn(v1.z, v1.w);
        ((uint4*)g_enc16)[i] = o;
    }
}

// ---------------------------------------------------------------------------
// Dominant kernel: fp16 mma.sync m16n8k16 GEMM with fused tanh/Va epilogue.
// KC=64 chunks, 3-stage cp.async pipeline, 2 CTA/SM.  (R13 verbatim)
// grid = (NBLK=8, BT/TM=512), block = 256 (8 warps of 64x32 tiles).
// ---------------------------------------------------------------------------
__global__ void __launch_bounds__(256, 2)
k_score_mma(const float* __restrict__ Va) {
    extern __shared__ __align__(16) char smem[];
    const uint32_t sb = smem_u32(smem);
    const int tid  = threadIdx.x;
    const int lane = tid & 31;
    const int wid  = tid >> 5;
    const int g    = lane >> 2;       // groupID
    const int tc   = lane & 3;        // threadID_in_group
    const int Mw   = wid & 1;         // warp M row (0/1)
    const int Nw   = wid >> 1;        // warp N col (0..3)

    const int u0 = blockIdx.x * TN;
    const int r0 = blockIdx.y * TM;
    const int b  = blockIdx.y >> 4;   // r0 / TT

    const __half* Ag = g_enc16 + (size_t)r0 * HH;
    const __half* Bg = g_UaT16 + (size_t)u0 * HH;

    // staging: 128 rows x 8 granules (16B) per tile; 4 A + 4 B per thread/stage
    const int st_row = tid >> 3, st_g = tid & 7;

    float d[4][4][4] = {};   // [Mtile][Ntile][reg]

    // ---- prologue: stage chunks 0,1 ----
    #pragma unroll
    for (int st = 0; st < STAGES - 1; ++st) {
        const uint32_t ab = sb + st * BUFBYTES;
        const int k0 = st * KC;
        #pragma unroll
        for (int j = 0; j < 4; ++j) {
            int row = st_row + 32 * j;
            cpasync16(ab + row * PITCHB + st_g * 16,
                      Ag + (size_t)row * HH + k0 + st_g * 8);
            cpasync16(ab + TILEB + row * PITCHB + st_g * 16,
                      Bg + (size_t)row * HH + k0 + st_g * 8);
        }
        asm volatile("cp.async.commit_group;" ::: "memory");
    }

    // per-lane fragment base offsets (bytes, within a buffer)
    const uint32_t aLane = (uint32_t)((Mw * 64 + g) * PITCHB + tc * 4);
    const uint32_t bLane = (uint32_t)((Nw * 32 + g) * PITCHB + tc * 4);

    int cur = 0, nxt = STAGES - 1;
    for (int c = 0; c < NCHUNK; ++c) {
        if (c + 1 < NCHUNK)
            asm volatile("cp.async.wait_group 1;" ::: "memory");
        else
            asm volatile("cp.async.wait_group 0;" ::: "memory");
        __syncthreads();

        // issue stage c+2 (buffer last read in chunk c-1; safe after sync)
        if (c + STAGES - 1 < NCHUNK) {
            const uint32_t ab = sb + nxt * BUFBYTES;
            const int k0 = (c + STAGES - 1) * KC;
            #pragma unroll
            for (int j = 0; j < 4; ++j) {
                int row = st_row + 32 * j;
                cpasync16(ab + row * PITCHB + st_g * 16,
                          Ag + (size_t)row * HH + k0 + st_g * 8);
                cpasync16(ab + TILEB + row * PITCHB + st_g * 16,
                          Bg + (size_t)row * HH + k0 + st_g * 8);
            }
            asm volatile("cp.async.commit_group;" ::: "memory");
        }

        // ---- compute chunk c from buffer cur: 4 K-steps of 16 ----
        const uint32_t bufo = cur * BUFBYTES;
        #pragma unroll
        for (int s = 0; s < 4; ++s) {
            uint32_t a[4][4];
            #pragma unroll
            for (int i = 0; i < 4; ++i) {
                const char* p = smem + bufo + aLane + i * 16 * PITCHB + s * 32;
                a[i][0] = *(const uint32_t*)(p);
                a[i][1] = *(const uint32_t*)(p + 8 * PITCHB);
                a[i][2] = *(const uint32_t*)(p + 16);
                a[i][3] = *(const uint32_t*)(p + 8 * PITCHB + 16);
            }
            #pragma unroll
            for (int jn = 0; jn < 4; ++jn) {
                const char* q = smem + bufo + TILEB + bLane
                              + jn * 8 * PITCHB + s * 32;
                uint32_t b0 = *(const uint32_t*)(q);
                uint32_t b1 = *(const uint32_t*)(q + 16);
                #pragma unroll
                for (int i = 0; i < 4; ++i)
                    mma_f16(d[i][jn], a[i], b0, b1);
            }
        }
        cur = (cur == STAGES - 1) ? 0 : cur + 1;
        nxt = (nxt == STAGES - 1) ? 0 : nxt + 1;
    }

    // ---- fused epilogue: tanh(d + dec)*Va, reduce over u ----
    float vdec[4][2], vva[4][2];
    #pragma unroll
    for (int jn = 0; jn < 4; ++jn)
        #pragma unroll
        for (int rr = 0; rr < 2; ++rr) {
            int ul = Nw * 32 + jn * 8 + tc * 2 + rr;
            vdec[jn][rr] = g_dec_proj[b * UU + u0 + ul];
            vva[jn][rr]  = Va[u0 + ul];
        }

    float rowacc[4][2] = {};
    #pragma unroll
    for (int i = 0; i < 4; ++i)
        #pragma unroll
        for (int jn = 0; jn < 4; ++jn)
            #pragma unroll
            for (int r = 0; r < 4; ++r) {
                float v = tanh_fast(d[i][jn][r] + vdec[jn][r & 1]) * vva[jn][r & 1];
                rowacc[i][r >> 1] += v;
            }
    #pragma unroll
    for (int i = 0; i < 4; ++i)
        #pragma unroll
        for (int h = 0; h < 2; ++h) {
            float v = rowacc[i][h];
            v += __shfl_xor_sync(0xffffffffu, v, 1);
            v += __shfl_xor_sync(0xffffffffu, v, 2);
            rowacc[i][h] = v;
        }

    // s_red aliases stage buffer 0 — wait for all warps to finish the mainloop
    __syncthreads();
    float* s_red = (float*)smem;
    if (tc == 0) {
        #pragma unroll
        for (int i = 0; i < 4; ++i)
            #pragma unroll
            for (int h = 0; h < 2; ++h) {
                int m = Mw * 64 + i * 16 + h * 8 + g;
                s_red[m * 4 + Nw] = rowacc[i][h];
            }
    }
    __syncthreads();
    if (tid < TM) {
        float s = s_red[tid * 4] + s_red[tid * 4 + 1]
                + s_red[tid * 4 + 2] + s_red[tid * 4 + 3];
        g_score_part[blockIdx.x][r0 + tid] = s;
    }
}

// ---------------------------------------------------------------------------
// Softmax over T (sums the 8 N-block partials). grid (B), 512 thr.
// ---------------------------------------------------------------------------
__global__ __launch_bounds__(512) void k_softmax() {
    int b = blockIdx.x, tid = threadIdx.x;
    __shared__ float sm[512];
    float* sc = g_score + b * TT;

    float m = -1e30f;
    for (int t = tid; t < TT; t += 512) {
        float v = 0.f;
        #pragma unroll
        for (int p = 0; p < NBLK; ++p) v += g_score_part[p][b * TT + t];
        sc[t] = v;
        m = fmaxf(m, v);
    }
    sm[tid] = m; __syncthreads();
    for (int s = 256; s > 0; s >>= 1) {
        if (tid < s) sm[tid] = fmaxf(sm[tid], sm[tid + s]);
        __syncthreads();
    }
    m = sm[0]; __syncthreads();

    float sum = 0.f;
    for (int t = tid; t < TT; t += 512) {
        float e = __expf(sc[t] - m);
        sc[t] = e; sum += e;
    }
    sm[tid] = sum; __syncthreads();
    for (int s = 256; s > 0; s >>= 1) {
        if (tid < s) sm[tid] += sm[tid + s];
        __syncthreads();
    }
    float inv = 1.f / sm[0];
    for (int t = tid; t < TT; t += 512) sc[t] *= inv;
}

// ---------------------------------------------------------------------------
// Context from fp16 enc: grid (B, 2, 16), block 256.
// Each block: 128 t's for 512 h's (half2 per thread).  (R13 verbatim)
// ---------------------------------------------------------------------------
__global__ __launch_bounds__(256) void k_ctx_part() {
    int b = blockIdx.x, hc = blockIdx.y, tc = blockIdx.z;
    int t0 = tc * 128;
    __shared__ float s_al[128];
    if (threadIdx.x < 128) s_al[threadIdx.x] = g_score[b * TT + t0 + threadIdx.x];
    __syncthreads();

    const __half2* e = (const __half2*)g_enc16
                     + ((size_t)b * TT + t0) * (HH/2) + hc * 256 + threadIdx.x;
    float ax = 0.f, ay = 0.f;
    #pragma unroll 16
    for (int t = 0; t < 128; ++t) {
        float2 f = __half22float2(e[(size_t)t * (HH/2)]);
        ax += s_al[t] * f.x;
        ay += s_al[t] * f.y;
    }
    int h2 = hc * 256 + threadIdx.x;
    ((float2*)&g_ctx_part[tc][b * HH])[h2] = make_float2(ax, ay);
}

__global__ __launch_bounds__(256) void k_ctx_final(float* __restrict__ out) {
    int idx = blockIdx.x * 256 + threadIdx.x;
    float s = 0.f;
    #pragma unroll
    for (int p = 0; p < 16; ++p) s += g_ctx_part[p][idx];
    out[idx] = s;
}

// ---------------------------------------------------------------------------
extern "C" void kernel_launch(void* const* d_in, const int* in_sizes, int n_in,
                              void* d_out, int out_size) {
    const float* enc = (const float*)d_in[0];
    const float* dec = (const float*)d_in[1];
    const float* Wa  = (const float*)d_in[2];
    const float* Ua  = (const float*)d_in[3];
    const float* Va  = (const float*)d_in[4];
    float* out = (float*)d_out;

    cudaFuncSetAttribute(k_score_mma,
                         cudaFuncAttributeMaxDynamicSharedMemorySize,
                         SMEM_TOTAL);

    k_prep<<<1152 + (BT * (HH / 8)) / 256, 256>>>(enc, dec, Wa, Ua);
    k_score_mma<<<dim3(NBLK, BT / TM), 256, SMEM_TOTAL>>>(Va);
    k_softmax<<<BB, 512>>>();
    k_ctx_part<<<dim3(BB, 2, 16), 256>>>();
    k_ctx_final<<<(BB * HH) / 256, 256>>>(out);
}